// round 12
// baseline (speedup 1.0000x reference)
#include <cuda_runtime.h>
#include <cstdint>

// B=1, H=32, L=8192, D=128, S=16384, GLOBAL_TOKENS=4
// keep[i] = i (i<4) else i+8192
// out layout (float32): k_out [H,L,D] | v_out [H,L,D] | pos_out [L]
//
// Converged family (R4/R8/R9/R11): UNROLL=8 front-batched LDG.128.cs,
// TPB=256, grid (128,32,2); 73.9-75.1us kernel, DRAM 81-83% = mixed 1:1
// R/W HBM3e ceiling. R12 probe: write-through stores (__stwt) — the one
// untested store cache-op (vs .cs best, write-back worse).

#define H_ 32
#define L_ 8192
#define D_ 128
#define S_ 16384
#define GTOK 4
#define F4_ROW (D_ / 4)                 // 32 float4 per row
#define F4_PER_HEAD_DST (L_ * F4_ROW)   // 262144
#define F4_PER_HEAD_SRC (S_ * F4_ROW)   // 524288
#define NK ((size_t)H_ * L_ * D_)       // 33554432 floats per tensor

#define UNROLL 8
#define TPB 256
#define TILE (TPB * UNROLL)             // 2048 float4 per block-tile

__global__ __launch_bounds__(TPB) void kvwindow_gather_kernel(
        const float4* __restrict__ k_val,
        const float4* __restrict__ v_val,
        const int*    __restrict__ input_pos,
        float4*       __restrict__ out4) {
    const int h = blockIdx.y;     // 0..31
    const int z = blockIdx.z;     // 0 = K, 1 = V

    const int base = blockIdx.x * TILE + threadIdx.x;   // within head (float4 units)
    const float4* __restrict__ srcp = z ? v_val : k_val;
    const size_t src_head = (size_t)h * F4_PER_HEAD_SRC;
    const size_t dst_head = (size_t)z * (NK / 4) + (size_t)h * F4_PER_HEAD_DST;

    // Front-batched independent loads (MLP = UNROLL), streaming-read hint
    float4 r[UNROLL];
#pragma unroll
    for (int u = 0; u < UNROLL; u++) {
        const int idx = base + u * TPB;
        const int src_shift = (idx < GTOK * F4_ROW) ? 0 : ((S_ - L_) * F4_ROW);
        r[u] = __ldcs(srcp + src_head + (size_t)idx + src_shift);
    }
    // Write-through stores: keep the write stream out of L2 entirely.
#pragma unroll
    for (int u = 0; u < UNROLL; u++) {
        const int idx = base + u * TPB;
        __stwt(out4 + dst_head + idx, r[u]);
    }

    // pos_out: fold into (z=0, h=0) slice — covers j in [0, L_)
    if (z == 0 && h == 0 && base < L_) {
#pragma unroll
        for (int u = 0; u < UNROLL; u++) {
            const int j = base + u * TPB;
            if (j < L_) {
                float* pos_out = reinterpret_cast<float*>(out4) + 2 * NK;
                int p = input_pos[(j < GTOK) ? j : (j + (S_ - L_))];
                if (p >= 0 && p < GTOK) p = 1000000000;
                pos_out[j] = (float)p;
            }
        }
    }
}

extern "C" void kernel_launch(void* const* d_in, const int* in_sizes, int n_in,
                              void* d_out, int out_size) {
    // metadata order: k_cache, v_cache, k_val, v_val, pos, input_pos
    const float4* k_val = (const float4*)d_in[2];
    const float4* v_val = (const float4*)d_in[3];
    const int* input_pos = (const int*)d_in[5];
    float4* out4 = (float4*)d_out;

    dim3 block(TPB);
    dim3 grid(F4_PER_HEAD_DST / TILE, H_, 2);  // (128, 32, 2) = 8192 blocks
    kvwindow_gather_kernel<<<grid, block>>>(k_val, v_val, input_pos, out4);
}

// round 13
// speedup vs baseline: 1.0160x; 1.0160x over previous
#include <cuda_runtime.h>
#include <cstdint>

// B=1, H=32, L=8192, D=128, S=16384, GLOBAL_TOKENS=4
// keep[i] = i (i<4) else i+8192
// out layout (float32): k_out [H,L,D] | v_out [H,L,D] | pos_out [L]
//
// FINAL (converged, R4/R8/R9/R11): UNROLL=8 front-batched LDG.128.cs +
// STG.128.cs, TPB=256, grid (128,32,2). 73.9-75.1us kernel over four
// reproductions; DRAM 81-83% / ~6.5 TB/s = mixed 1:1 R/W HBM3e ceiling on
// GB300. Full design-space sweep, each axis in isolation:
//   MLP {1,4,8,16} -> 8; TPB {128,256,512} -> 256;
//   stores {.cs, write-back, .wt} -> .cs; index {select, fixup} -> select.
// Traffic minimal (each byte read once, written once); issue<=7% (latency
// fully hidden); no compute. No positive lever remains on this hardware.

#define H_ 32
#define L_ 8192
#define D_ 128
#define S_ 16384
#define GTOK 4
#define F4_ROW (D_ / 4)                 // 32 float4 per row
#define F4_PER_HEAD_DST (L_ * F4_ROW)   // 262144
#define F4_PER_HEAD_SRC (S_ * F4_ROW)   // 524288
#define NK ((size_t)H_ * L_ * D_)       // 33554432 floats per tensor

#define UNROLL 8
#define TPB 256
#define TILE (TPB * UNROLL)             // 2048 float4 per block-tile

__global__ __launch_bounds__(TPB) void kvwindow_gather_kernel(
        const float4* __restrict__ k_val,
        const float4* __restrict__ v_val,
        const int*    __restrict__ input_pos,
        float4*       __restrict__ out4) {
    const int h = blockIdx.y;     // 0..31
    const int z = blockIdx.z;     // 0 = K, 1 = V

    const int base = blockIdx.x * TILE + threadIdx.x;   // within head (float4 units)
    const float4* __restrict__ srcp = z ? v_val : k_val;
    const size_t src_head = (size_t)h * F4_PER_HEAD_SRC;
    const size_t dst_head = (size_t)z * (NK / 4) + (size_t)h * F4_PER_HEAD_DST;

    // Front-batched independent loads (MLP = UNROLL)
    float4 r[UNROLL];
#pragma unroll
    for (int u = 0; u < UNROLL; u++) {
        const int idx = base + u * TPB;
        const int src_shift = (idx < GTOK * F4_ROW) ? 0 : ((S_ - L_) * F4_ROW);
        r[u] = __ldcs(srcp + src_head + (size_t)idx + src_shift);
    }
#pragma unroll
    for (int u = 0; u < UNROLL; u++) {
        const int idx = base + u * TPB;
        __stcs(out4 + dst_head + idx, r[u]);
    }

    // pos_out: fold into (z=0, h=0) slice — covers j in [0, L_)
    if (z == 0 && h == 0 && base < L_) {
#pragma unroll
        for (int u = 0; u < UNROLL; u++) {
            const int j = base + u * TPB;
            if (j < L_) {
                float* pos_out = reinterpret_cast<float*>(out4) + 2 * NK;
                int p = input_pos[(j < GTOK) ? j : (j + (S_ - L_))];
                if (p >= 0 && p < GTOK) p = 1000000000;
                pos_out[j] = (float)p;
            }
        }
    }
}

extern "C" void kernel_launch(void* const* d_in, const int* in_sizes, int n_in,
                              void* d_out, int out_size) {
    // metadata order: k_cache, v_cache, k_val, v_val, pos, input_pos
    const float4* k_val = (const float4*)d_in[2];
    const float4* v_val = (const float4*)d_in[3];
    const int* input_pos = (const int*)d_in[5];
    float4* out4 = (float4*)d_out;

    dim3 block(TPB);
    dim3 grid(F4_PER_HEAD_DST / TILE, H_, 2);  // (128, 32, 2) = 8192 blocks
    kvwindow_gather_kernel<<<grid, block>>>(k_val, v_val, input_pos, out4);
}